// round 17
// baseline (speedup 1.0000x reference)
#include <cuda_runtime.h>
#include <cstdint>

// ERGCNLayer: out[n] = h[n] + sum_{k: dst[k]=n} ( h[src[k]]*weight[rel[k]] + e[k]*attention[rel[k]] )
// N=100000, E=1600000, D=64, R=200
// d_in: 0=h 1=e 2=weight 3=attention 4=src 5=dst 6=rel ; out f32[N,64]
//
// Two-phase, LTS-minimized:
//   build  : bucket edges by dst -> packed int2 {edge, src|rel<<17} (counters pre-zeroed)
//   gather : grid-stride warps, w/a staged in smem, out = h + acc plain write;
//            resets g_cnt for the next replay (no separate zero kernel)
//   fixup  : replay rare CAP-overflow edges; resets overflow counter

#define D 64
#define NN 100000
#define CAP 64               // in-degree slots; Poisson(16) => P(>64) ~ 0
#define MAXOVF 8192
#define F2_PER_ROW 32
#define SRC_BITS 17
#define SRC_MASK ((1 << SRC_BITS) - 1)
#define BLOCK 512
#define WPB (BLOCK / 32)     // 16 warps per block
#define GRID 296             // 2 blocks/SM x 148 SMs

__device__ int  g_cnt[NN];                 // zero at module load; each replay re-zeroes
__device__ int2 g_lst[(size_t)NN * CAP];   // {edge, src | rel<<17}
__device__ int  g_ovf_cnt;                 // zero at module load; fixup re-zeroes
__device__ int  g_ovf[MAXOVF];

__global__ void build_kernel(const int* __restrict__ src,
                             const int* __restrict__ dst,
                             const int* __restrict__ rel,
                             int E) {
    int k = blockIdx.x * blockDim.x + threadIdx.x;
    if (k >= E) return;
    int d = dst[k];
    int pos = atomicAdd(&g_cnt[d], 1);
    if (pos < CAP) {
        g_lst[(size_t)d * CAP + pos] = make_int2(k, src[k] | (rel[k] << SRC_BITS));
    } else {
        int op = atomicAdd(&g_ovf_cnt, 1);
        if (op < MAXOVF) g_ovf[op] = k;
    }
}

// Grid-stride warps over nodes. w/a live in smem (off the LTS path).
__global__ void __launch_bounds__(BLOCK, 2)
gather_kernel(const float2* __restrict__ h2,
              const float2* __restrict__ e2,
              const float2* __restrict__ w2,
              const float2* __restrict__ a2,
              float2* __restrict__ out2, int Nn, int R) {
    extern __shared__ float2 sm[];
    float2* w_s = sm;                       // [R * F2_PER_ROW]
    float2* a_s = sm + (size_t)R * F2_PER_ROW;
    for (int i = threadIdx.x; i < R * F2_PER_ROW; i += BLOCK) {
        w_s[i] = __ldg(w2 + i);
        a_s[i] = __ldg(a2 + i);
    }
    __syncthreads();

    int lane = threadIdx.x & 31;
    int gw   = blockIdx.x * WPB + (threadIdx.x >> 5);
    int tot  = gridDim.x * WPB;

    for (int node = gw; node < Nn; node += tot) {
        int deg_raw = g_cnt[node];
        int deg = deg_raw > CAP ? CAP : deg_raw;
        const int2* lst = g_lst + (size_t)node * CAP;

        float accx = 0.f, accy = 0.f;
        int i = 0;
        for (; i + 4 <= deg; i += 4) {       // 8 independent global row-loads in flight
            int2 t0 = lst[i + 0], t1 = lst[i + 1], t2 = lst[i + 2], t3 = lst[i + 3];
            int s0 = t0.y & SRC_MASK, r0 = t0.y >> SRC_BITS;
            int s1 = t1.y & SRC_MASK, r1 = t1.y >> SRC_BITS;
            int s2 = t2.y & SRC_MASK, r2 = t2.y >> SRC_BITS;
            int s3 = t3.y & SRC_MASK, r3 = t3.y >> SRC_BITS;
            float2 E0 = __ldcs(e2 + (size_t)t0.x * F2_PER_ROW + lane);
            float2 E1 = __ldcs(e2 + (size_t)t1.x * F2_PER_ROW + lane);
            float2 E2 = __ldcs(e2 + (size_t)t2.x * F2_PER_ROW + lane);
            float2 E3 = __ldcs(e2 + (size_t)t3.x * F2_PER_ROW + lane);
            float2 H0 = __ldg(h2 + (size_t)s0 * F2_PER_ROW + lane);
            float2 H1 = __ldg(h2 + (size_t)s1 * F2_PER_ROW + lane);
            float2 H2 = __ldg(h2 + (size_t)s2 * F2_PER_ROW + lane);
            float2 H3 = __ldg(h2 + (size_t)s3 * F2_PER_ROW + lane);
            float2 W0 = w_s[r0 * F2_PER_ROW + lane];
            float2 W1 = w_s[r1 * F2_PER_ROW + lane];
            float2 W2 = w_s[r2 * F2_PER_ROW + lane];
            float2 W3 = w_s[r3 * F2_PER_ROW + lane];
            float2 A0 = a_s[r0 * F2_PER_ROW + lane];
            float2 A1 = a_s[r1 * F2_PER_ROW + lane];
            float2 A2 = a_s[r2 * F2_PER_ROW + lane];
            float2 A3 = a_s[r3 * F2_PER_ROW + lane];
            accx = fmaf(H0.x, W0.x, accx); accx = fmaf(E0.x, A0.x, accx);
            accy = fmaf(H0.y, W0.y, accy); accy = fmaf(E0.y, A0.y, accy);
            accx = fmaf(H1.x, W1.x, accx); accx = fmaf(E1.x, A1.x, accx);
            accy = fmaf(H1.y, W1.y, accy); accy = fmaf(E1.y, A1.y, accy);
            accx = fmaf(H2.x, W2.x, accx); accx = fmaf(E2.x, A2.x, accx);
            accy = fmaf(H2.y, W2.y, accy); accy = fmaf(E2.y, A2.y, accy);
            accx = fmaf(H3.x, W3.x, accx); accx = fmaf(E3.x, A3.x, accx);
            accy = fmaf(H3.y, W3.y, accy); accy = fmaf(E3.y, A3.y, accy);
        }
        for (; i < deg; i++) {
            int2 t = lst[i];
            int s = t.y & SRC_MASK, r = t.y >> SRC_BITS;
            float2 Ev = __ldcs(e2 + (size_t)t.x * F2_PER_ROW + lane);
            float2 Hv = __ldg(h2 + (size_t)s * F2_PER_ROW + lane);
            float2 Wv = w_s[r * F2_PER_ROW + lane];
            float2 Av = a_s[r * F2_PER_ROW + lane];
            accx = fmaf(Hv.x, Wv.x, accx); accx = fmaf(Ev.x, Av.x, accx);
            accy = fmaf(Hv.y, Wv.y, accy); accy = fmaf(Ev.y, Av.y, accy);
        }

        size_t oidx = (size_t)node * F2_PER_ROW + lane;
        float2 hrow = __ldg(h2 + oidx);
        out2[oidx] = make_float2(hrow.x + accx, hrow.y + accy);

        if (lane == 0) g_cnt[node] = 0;      // restore invariant for next replay
    }
}

// Replay overflow edges (expected 0) with v2 REDs; reset overflow counter.
__global__ void fixup_kernel(const int* __restrict__ src,
                             const int* __restrict__ dst,
                             const int* __restrict__ rel,
                             const float2* __restrict__ h2,
                             const float2* __restrict__ e2,
                             const float2* __restrict__ w2,
                             const float2* __restrict__ a2,
                             float* __restrict__ out) {
    int cnt = g_ovf_cnt;
    if (cnt > MAXOVF) cnt = MAXOVF;
    __syncthreads();
    int warp = threadIdx.x >> 5;             // 8 warps, single block
    int lane = threadIdx.x & 31;
    for (int i = warp; i < cnt; i += 8) {
        int k = g_ovf[i];
        int s = src[k], d = dst[k], r = rel[k];
        float2 Ev = e2[(size_t)k * F2_PER_ROW + lane];
        float2 Hv = h2[(size_t)s * F2_PER_ROW + lane];
        float2 Wv = w2[(size_t)r * F2_PER_ROW + lane];
        float2 Av = a2[(size_t)r * F2_PER_ROW + lane];
        float mx = fmaf(Hv.x, Wv.x, Ev.x * Av.x);
        float my = fmaf(Hv.y, Wv.y, Ev.y * Av.y);
        asm volatile("red.global.add.v2.f32 [%0], {%1, %2};"
                     :: "l"(out + (size_t)d * D + lane * 2), "f"(mx), "f"(my)
                     : "memory");
    }
    __syncthreads();
    if (threadIdx.x == 0) g_ovf_cnt = 0;     // restore invariant for next replay
}

extern "C" void kernel_launch(void* const* d_in, const int* in_sizes, int n_in,
                              void* d_out, int out_size) {
    const float* h  = (const float*)d_in[0];
    const float* e  = (const float*)d_in[1];
    const float* w  = (const float*)d_in[2];
    const float* a  = (const float*)d_in[3];
    const int* src  = (const int*)d_in[4];
    const int* dst  = (const int*)d_in[5];
    const int* rel  = (const int*)d_in[6];
    float* out      = (float*)d_out;

    int E  = in_sizes[4];
    int R  = in_sizes[2] / D;                // 200
    int Nn = out_size / D;

    size_t smem_bytes = (size_t)2 * R * F2_PER_ROW * sizeof(float2);  // 102,400
    static bool attr_set = false;
    if (!attr_set) {
        cudaFuncSetAttribute(gather_kernel,
                             cudaFuncAttributeMaxDynamicSharedMemorySize,
                             (int)smem_bytes);
        attr_set = true;
    }

    build_kernel<<<(E + 255) / 256, 256>>>(src, dst, rel, E);
    gather_kernel<<<GRID, BLOCK, smem_bytes>>>(
        (const float2*)h, (const float2*)e, (const float2*)w, (const float2*)a,
        (float2*)out, Nn, R);
    fixup_kernel<<<1, 256>>>(src, dst, rel,
                             (const float2*)h, (const float2*)e,
                             (const float2*)w, (const float2*)a, out);
}